// round 10
// baseline (speedup 1.0000x reference)
#include <cuda_runtime.h>
#include <cstdint>
#include <math.h>

// Problem shape (fixed): N=16, T=256, U=128, V=256, blank = V-1.
#define N_  16
#define T_  256
#define U_  128
#define V_  256
#define DD  383             // anti-diagonals d = 0..382
#define DD_PAD 400
#define NEGF (-1e30f)

#define NCTAS   148
#define NUNITS  1168        // gather units (128 threads each): 16*7 + 132*8
#define NTASKS  (N_ * 384)  // row-tasks: r in [1,384] x n in [0,16)

// Scratch (allocation-free rule: __device__ globals, zero-initialized).
// SHIFTED diagonal-major layout: blank(n,t,u) at [n][t+u+1][u]; emit(n,t,u) at
// [n][t+u+1][u+1]. Unwritten slots stay 0 and only combine with NEG alphas.
__device__ __align__(16) float g_blank[N_ * DD_PAD * U_];
__device__ __align__(16) float g_emit [N_ * DD_PAD * U_];
__device__ float    g_cost[N_];
// Counting epoch flags: every row flag gains EXACTLY 128 per launch (one
// release-red per writer thread), so "flag >= 128*ep" is a reset-free ready
// test across graph replays. Cost flags gain 1 per launch.
__device__ unsigned g_rowflag [N_ * DD_PAD];   // [n*DD_PAD + r]
__device__ unsigned g_costflag[N_];
__device__ unsigned g_dpep    [N_];

// ---- sync helpers ----------------------------------------------------------
__device__ __forceinline__ unsigned ld_acq_u32(const unsigned* p) {
    unsigned v;
    asm volatile("ld.acquire.gpu.global.u32 %0, [%1];" : "=r"(v) : "l"(p) : "memory");
    return v;
}
__device__ __forceinline__ uint4 ld_acq_v4(const unsigned* p) {
    uint4 v;
    asm volatile("ld.acquire.gpu.global.v4.u32 {%0,%1,%2,%3}, [%4];"
                 : "=r"(v.x), "=r"(v.y), "=r"(v.z), "=r"(v.w) : "l"(p) : "memory");
    return v;
}
__device__ __forceinline__ void red_rel_add1(unsigned* p) {
    asm volatile("red.release.gpu.global.add.u32 [%0], 1;" :: "l"(p) : "memory");
}
__device__ __forceinline__ bool ok4(uint4 f, unsigned epm) {
    return f.x >= epm && f.y >= epm && f.z >= epm && f.w >= epm;
}

// ---------------------------------------------------------------------------
// Gather unit: 128 threads; 2 super-iterations x 4 row-tasks, 8 front-batched
// scattered loads per thread per super-iteration. Task t -> (r=1+t/16, n=t%16).
// NO fences, NO barriers: each thread release-reds the row flag right after
// its own 2 stores; red is no-return so the load pipeline never drains.
// ---------------------------------------------------------------------------
__device__ void gather_unit(const float* __restrict__ lp,
                            const int*   __restrict__ labels,
                            int unit, int lt)
{
    const int c = lt;                       // column 0..127
    for (int s = 0; s < 2; ++s) {
        float vb[4], ve[4];
#pragma unroll
        for (int j = 0; j < 4; ++j) {
            int t  = unit + NUNITS * (4 * s + j);
            int tv = t < NTASKS ? t : NTASKS - 1;
            int r  = 1 + (tv >> 4);
            int n  = tv & 15;
            int tb = r - 1 - c;                       // blank(t=tb, u=c)
            int te = r - c;                           // emit (t=te, u=c-1)
            int tbc = tb < 0 ? 0 : (tb > T_ - 1 ? T_ - 1 : tb);
            int tec = te < 0 ? 0 : (te > T_ - 1 ? T_ - 1 : te);
            int lbl = (c >= 1) ? __ldg(&labels[n * (U_ - 1) + (c - 1)]) : 0;
            vb[j] = __ldcs(lp + ((((size_t)n * T_ + tbc) * U_ + c) * V_) + (V_ - 1));
            ve[j] = __ldcs(lp + ((((size_t)n * T_ + tec) * U_ + (c - (c >= 1))) * V_) + lbl);
        }
#pragma unroll
        for (int j = 0; j < 4; ++j) {
            int t = unit + NUNITS * (4 * s + j);
            if (t >= NTASKS) continue;
            int r = 1 + (t >> 4);
            int n = t & 15;
            int tb = r - 1 - c;
            int te = r - c;
            size_t rowbase = ((size_t)n * DD_PAD + r) * U_;
            if (tb >= 0 && tb < T_)           g_blank[rowbase + c] = vb[j];
            if (c >= 1 && te >= 0 && te < T_) g_emit [rowbase + c] = ve[j];
            red_rel_add1(&g_rowflag[n * DD_PAD + r]);   // releases the 2 stores
        }
    }
}

// ---------------------------------------------------------------------------
// DP warp: one warp, example n, 4 u-columns per thread, cp.async 16-slot ring,
// flag-gated row issue, flag reads prefetched one group ahead.
// ---------------------------------------------------------------------------
__device__ __forceinline__ float lse2(float a, float b) {
    float mx = fmaxf(a, b);
    float mn = fminf(a, b);
    return mx + 0.6931471805599453f *
                __log2f(1.0f + exp2f((mn - mx) * 1.4426950408889634f));
}

#define DP_STEP(bv, ev, dcur)                                                 \
    {                                                                         \
        float la = __shfl_up_sync(0xffffffffu, a3, 1);                        \
        float l0 = (tx == 0) ? NEGF : la;                                     \
        float n0 = lse2(a0 + (bv).x, l0 + (ev).x);                            \
        float n1 = lse2(a1 + (bv).y, a0 + (ev).y);                            \
        float n2 = lse2(a2 + (bv).z, a1 + (ev).z);                            \
        float n3 = lse2(a3 + (bv).w, a2 + (ev).w);                            \
        a0 = n0; a1 = n1; a2 = n2; a3 = n3;                                   \
        if ((dcur) == target && cap)                                          \
            saved = (ci == 0) ? n0 : (ci == 1) ? n1 : (ci == 2) ? n2 : n3;    \
    }

#define ISSUE_ROW(rr)                                                         \
    {                                                                         \
        int _rrc = (rr) < (DD_PAD - 1) ? (rr) : (DD_PAD - 1);                 \
        unsigned _slot = ((unsigned)(rr) & 15u) * (U_ * 4u) + lane_off;       \
        const float* _gb = bl + (size_t)_rrc * U_ + 4 * tx;                   \
        const float* _ge = em + (size_t)_rrc * U_ + 4 * tx;                   \
        asm volatile("cp.async.ca.shared.global [%0], [%1], 16;"              \
                     :: "r"(sb_base + _slot), "l"(_gb));                      \
        asm volatile("cp.async.ca.shared.global [%0], [%1], 16;"              \
                     :: "r"(se_base + _slot), "l"(_ge));                      \
    }

#define DP_PAIR(p)                                                            \
    {                                                                         \
        asm volatile("cp.async.wait_group 6;" ::: "memory");                  \
        ISSUE_ROW(2 * (p) + 15);                                              \
        ISSUE_ROW(2 * (p) + 16);                                              \
        asm volatile("cp.async.commit_group;" ::: "memory");                  \
        const int _d1 = 2 * (p) + 1;                                          \
        {                                                                     \
            const int _s = _d1 & 15;                                          \
            float4 b = *(const float4*)&sb[_s * U_ + 4 * tx];                 \
            float4 e = *(const float4*)&se[_s * U_ + 4 * tx];                 \
            DP_STEP(b, e, _d1);                                               \
        }                                                                     \
        {                                                                     \
            const int _d2 = _d1 + 1;                                          \
            const int _s = _d2 & 15;                                          \
            float4 b = *(const float4*)&sb[_s * U_ + 4 * tx];                 \
            float4 e = *(const float4*)&se[_s * U_ + 4 * tx];                 \
            DP_STEP(b, e, _d2);                                               \
        }                                                                     \
    }

__device__ void dp_warp(const int* __restrict__ lengths,
                        const int* __restrict__ label_lengths,
                        int n, int tx, float* sb, float* se, float* out)
{
    unsigned ep;
    if (tx == 0) ep = atomicAdd(&g_dpep[n], 1u) + 1u;
    ep = __shfl_sync(0xffffffffu, ep, 0);
    const unsigned epm = ep * 128u;       // row-flag threshold (128 writers/row)

    const unsigned* flg = g_rowflag + n * DD_PAD;
    const float* __restrict__ bl = g_blank + (size_t)n * DD_PAD * U_;
    const float* __restrict__ em = g_emit  + (size_t)n * DD_PAD * U_;

    const int t_idx  = lengths[n] - 1;
    const int u_idx  = label_lengths[n];
    const int target = t_idx + u_idx;

    float a0 = (tx == 0) ? 0.0f : NEGF;
    float a1 = NEGF, a2 = NEGF, a3 = NEGF;
    float saved = 0.0f;
    const bool cap = (tx == (u_idx >> 2));
    const int  ci  = u_idx & 3;

    const unsigned sb_base = (unsigned)__cvta_generic_to_shared(sb);
    const unsigned se_base = (unsigned)__cvta_generic_to_shared(se);
    const unsigned lane_off = 16u * (unsigned)tx;

    // Initial: wait for rows 1..16 (lane-parallel spins).
    if (tx < 16) {
        while (ld_acq_u32(flg + (tx + 1)) < epm) __nanosleep(64);
    }
    __syncwarp();

    // Prologue: issue rows 1..14 (7 commit groups).
#pragma unroll
    for (int q = 0; q < 7; ++q) {
        ISSUE_ROW(2 * q + 1);
        ISSUE_ROW(2 * q + 2);
        asm volatile("cp.async.commit_group;" ::: "memory");
    }

    // Group g covers pairs 4g..4g+3 (issues rows 8g+15..8g+22); flag check
    // covers rows 8g+12..8g+23, prefetched one group ahead.
    uint4 f0 = ld_acq_v4(flg + 12), f1 = ld_acq_v4(flg + 16), f2 = ld_acq_v4(flg + 20);

    for (int g = 0; g < 45; ++g) {
        while (!(ok4(f0, epm) && ok4(f1, epm) && ok4(f2, epm))) {
            __nanosleep(64);
            int base = 8 * g + 12;
            f0 = ld_acq_v4(flg + base); f1 = ld_acq_v4(flg + base + 4); f2 = ld_acq_v4(flg + base + 8);
        }
        int nbase = (g < 44) ? (8 * g + 20) : 372;
        uint4 nf0 = ld_acq_v4(flg + nbase);
        uint4 nf1 = ld_acq_v4(flg + nbase + 4);
        uint4 nf2 = ld_acq_v4(flg + nbase + 8);

        const int p0 = 4 * g;
        DP_PAIR(p0); DP_PAIR(p0 + 1); DP_PAIR(p0 + 2); DP_PAIR(p0 + 3);

        f0 = nf0; f1 = nf1; f2 = nf2;
    }

    // Tail: confirm rows 372..384, then pairs 180..190 checkless.
    while (!(ok4(f0, epm) && ok4(f1, epm) && ok4(f2, epm))) {
        __nanosleep(64);
        f0 = ld_acq_v4(flg + 372); f1 = ld_acq_v4(flg + 376); f2 = ld_acq_v4(flg + 380);
    }
    while (ld_acq_u32(flg + 384) < epm) __nanosleep(64);

    for (int p = 180; p < 191; ++p) { DP_PAIR(p); }

    if (cap) {
        float bfin = bl[(size_t)(target + 1) * U_ + u_idx];  // blank(t_idx, u_idx)
        g_cost[n] = -(saved + bfin);
        __threadfence();
        red_rel_add1(&g_costflag[n]);
    }

    // Finalize (n==0 CTA, lane 0): deterministic serial mean.
    if (n == 0 && tx == 0) {
        float s = 0.0f;
#pragma unroll
        for (int i = 0; i < N_; ++i) {
            while (ld_acq_u32(&g_costflag[i]) < ep) __nanosleep(128);
            s += __ldcg(&g_cost[i]);
        }
        out[0] = s * (1.0f / N_);
    }
}

// ---------------------------------------------------------------------------
// Fused persistent kernel, 1024 threads/CTA.
//   CTA 0..15  : warp 0 = DP(example=cta); warpgroups 1..7 = gather units.
//   CTA 16..147: warpgroups 0..7 = gather units.
// Gather units never wait on anything -> unconditional forward progress; DP
// only waits on gather row flags.
// ---------------------------------------------------------------------------
__global__ void __launch_bounds__(1024) fused_kernel(const float* __restrict__ lp,
                                                     const int*   __restrict__ labels,
                                                     const int*   __restrict__ lengths,
                                                     const int*   __restrict__ label_lengths,
                                                     float* __restrict__ out)
{
    __shared__ __align__(16) float sb[16 * U_];
    __shared__ __align__(16) float se[16 * U_];

    const int cta = blockIdx.x;
    const int tid = threadIdx.x;
    const int wg  = tid >> 7;            // warpgroup 0..7
    const int lt  = tid & 127;

    if (cta < N_) {
        if (wg == 0) {
            if (tid < 32)
                dp_warp(lengths, label_lengths, cta, tid, sb, se, out);
            // warps 1..3 idle
        } else {
            gather_unit(lp, labels, cta * 7 + (wg - 1), lt);          // units 0..111
        }
    } else {
        gather_unit(lp, labels, 112 + (cta - 16) * 8 + wg, lt);       // units 112..1167
    }
}

// ---------------------------------------------------------------------------
extern "C" void kernel_launch(void* const* d_in, const int* in_sizes, int n_in,
                              void* d_out, int out_size)
{
    const float* log_probs     = (const float*)d_in[0];
    const int*   labels        = (const int*)  d_in[1];
    const int*   lengths       = (const int*)  d_in[2];
    const int*   label_lengths = (const int*)  d_in[3];
    float*       out           = (float*)d_out;

    fused_kernel<<<NCTAS, 1024>>>(log_probs, labels, lengths, label_lengths, out);
}

// round 11
// speedup vs baseline: 1.2371x; 1.2371x over previous
#include <cuda_runtime.h>
#include <cstdint>
#include <math.h>

// Problem shape (fixed): N=16, T=256, U=128, V=256, blank = V-1.
#define N_  16
#define T_  256
#define U_  128
#define V_  256
#define DD  383             // anti-diagonals d = 0..382
#define DD_PAD 400
#define NEGF (-1e30f)
#define LOG2E 1.4426950408889634f
#define LN2   0.6931471805599453f

// Scratch (allocation-free rule: __device__ globals, zero-initialized).
// SHIFTED diagonal-major layout, values PRE-SCALED by log2(e):
//   blank(n,t,u)*log2e at [n][t+u+1][u]; emit(n,t,u)*log2e at [n][t+u+1][u+1].
// Unwritten slots stay 0 and only ever combine with NEG alphas.
__device__ __align__(16) float g_blank[N_ * DD_PAD * U_];
__device__ __align__(16) float g_emit [N_ * DD_PAD * U_];
__device__ float g_cost[N_];

// ---------------------------------------------------------------------------
// Kernel 1: gather (R5 structure: coalesced writes, streaming reads).
// One block per (n, diagonal row r); lane c handles column c.
// ---------------------------------------------------------------------------
__global__ void __launch_bounds__(U_) gather_kernel(const float* __restrict__ lp,
                                                    const int*   __restrict__ labels)
{
    const int r = (blockIdx.x % DD) + 1;     // shifted row 1..383
    const int n = blockIdx.x / DD;
    const int c = threadIdx.x;               // column 0..127

    const size_t rowbase = ((size_t)n * DD_PAD + r) * U_;

    int tb = r - 1 - c;                       // blank(t=tb, u=c)
    if (tb >= 0 && tb < T_) {
        float v = __ldcs(lp + ((((size_t)n * T_ + tb) * U_ + c) * V_) + (V_ - 1));
        g_blank[rowbase + c] = v * LOG2E;
    }
    int te = r - c;                           // emit(t=te, u=c-1)
    if (c >= 1 && te >= 0 && te < T_) {
        int lbl = __ldg(&labels[n * (U_ - 1) + (c - 1)]);
        float v = __ldcs(lp + ((((size_t)n * T_ + te) * U_ + (c - 1)) * V_) + lbl);
        g_emit[rowbase + c] = v * LOG2E;
    }
}

// ---------------------------------------------------------------------------
// Kernel 2: skewed-wavefront DP. 4 warps per example (4 SMSPs), ONE column
// per lane (u = tid). Warp w processes diagonal d at phase d + 8w; boundary
// alphas cross warps through a 32-slot smem ring; one __syncthreads per
// 8 phases (write->read gap = 9 phases, read->overwrite gap = 23 phases).
// Operands flow through an 8-slot named-register ring (prefetch distance 8).
// ---------------------------------------------------------------------------
#define PHASE(k)                                                              \
    {                                                                         \
        const int d = P0 + (k) - 8 * w;                                       \
        if (d >= 1 && d <= DD - 1) {                                          \
            float b = rb##k, e = re##k;                                       \
            float la = __shfl_up_sync(0xffffffffu, a, 1);                     \
            float left = (lane == 0)                                          \
                             ? ((w == 0) ? NEGF : bnd[w - 1][(d - 1) & 31])   \
                             : la;                                            \
            float x = a + b;                                                  \
            float y = left + e;                                               \
            float mx = fmaxf(x, y);                                           \
            float z  = exp2f(-fabsf(x - y));                                  \
            a = mx + __log2f(1.0f + z);                                       \
            if (cap && d == target) saved = a;                                \
            if (lane == 31) bnd[w][d & 31] = a;                               \
        }                                                                     \
        {                                                                     \
            int rr = P0 + (k) - 8 * w + 8;                                    \
            rr = rr < 1 ? 1 : (rr > DD_PAD - 1 ? DD_PAD - 1 : rr);            \
            rb##k = __ldg(bl + (size_t)rr * U_ + u);                          \
            re##k = __ldg(em + (size_t)rr * U_ + u);                          \
        }                                                                     \
    }

#define PRELOAD(k)                                                            \
    float rb##k, re##k;                                                       \
    {                                                                         \
        int rr = (k) - 8 * w;                                                 \
        rr = rr < 1 ? 1 : rr;                                                 \
        rb##k = __ldg(bl + (size_t)rr * U_ + u);                              \
        re##k = __ldg(em + (size_t)rr * U_ + u);                              \
    }

__global__ void __launch_bounds__(128) dp_kernel(const int* __restrict__ lengths,
                                                 const int* __restrict__ label_lengths)
{
    __shared__ float bnd[4][32];   // [warp][diag & 31] lane-31 boundary alphas

    const int n    = blockIdx.x;
    const int tid  = threadIdx.x;
    const int w    = tid >> 5;
    const int lane = tid & 31;
    const int u    = tid;          // owned column

    bnd[w][lane] = NEGF;
    __syncthreads();

    const float* __restrict__ bl = g_blank + (size_t)n * DD_PAD * U_;
    const float* __restrict__ em = g_emit  + (size_t)n * DD_PAD * U_;

    const int t_idx  = __ldg(&lengths[n]) - 1;
    const int u_idx  = __ldg(&label_lengths[n]);
    const int target = t_idx + u_idx;

    float a     = (tid == 0) ? 0.0f : NEGF;   // alpha in log2 units
    float saved = 0.0f;
    const bool cap = (tid == u_idx);

    PRELOAD(0) PRELOAD(1) PRELOAD(2) PRELOAD(3)
    PRELOAD(4) PRELOAD(5) PRELOAD(6) PRELOAD(7)

    // Phases 0..407 in 51 groups of 8 (max needed phase: 382 + 24 = 406).
    for (int P0 = 0; P0 < 408; P0 += 8) {
        PHASE(0) PHASE(1) PHASE(2) PHASE(3)
        PHASE(4) PHASE(5) PHASE(6) PHASE(7)
        __syncthreads();
    }

    if (cap) {
        float bfin = __ldg(bl + (size_t)(target + 1) * U_ + u_idx); // blank(t_idx,u_idx)*log2e
        g_cost[n] = -(saved + bfin) * LN2;
    }
}

// ---------------------------------------------------------------------------
// Kernel 3: deterministic serial mean of the 16 per-example costs.
// ---------------------------------------------------------------------------
__global__ void finalize_kernel(float* __restrict__ out)
{
    float s = 0.0f;
#pragma unroll
    for (int i = 0; i < N_; ++i) s += g_cost[i];
    out[0] = s * (1.0f / N_);
}

// ---------------------------------------------------------------------------
extern "C" void kernel_launch(void* const* d_in, const int* in_sizes, int n_in,
                              void* d_out, int out_size)
{
    const float* log_probs     = (const float*)d_in[0];
    const int*   labels        = (const int*)  d_in[1];
    const int*   lengths       = (const int*)  d_in[2];
    const int*   label_lengths = (const int*)  d_in[3];
    float*       out           = (float*)d_out;

    gather_kernel  <<<N_ * DD, U_>>>(log_probs, labels);
    dp_kernel      <<<N_, 128>>>(lengths, label_lengths);
    finalize_kernel<<<1, 1>>>(out);
}

// round 12
// speedup vs baseline: 1.2572x; 1.0162x over previous
#include <cuda_runtime.h>
#include <cstdint>
#include <math.h>

// Problem shape (fixed): N=16, T=256, U=128, V=256, blank = V-1.
#define N_  16
#define T_  256
#define U_  128
#define V_  256
#define DD  383             // anti-diagonals d = 0..382
#define DD_PAD 400
#define NEGF (-1e30f)
#define LOG2E 1.4426950408889634f
#define LN2   0.6931471805599453f

// Scratch (allocation-free rule: __device__ globals, zero-initialized).
// SHIFTED diagonal-major layout, values PRE-SCALED by log2(e):
//   blank(n,t,u)*log2e at [n][t+u+1][u]; emit(n,t,u)*log2e at [n][t+u+1][u+1].
// Unwritten slots stay 0 and only ever combine with NEG alphas.
__device__ __align__(16) float g_blank[N_ * DD_PAD * U_];
__device__ __align__(16) float g_emit [N_ * DD_PAD * U_];
__device__ float g_cost[N_];

// MUFU EX2 (plain exp2f is a SLOW software routine without fast-math!).
__device__ __forceinline__ float ex2_fast(float x) {
    float y;
    asm("ex2.approx.ftz.f32 %0, %1;" : "=f"(y) : "f"(x));
    return y;
}

// ---------------------------------------------------------------------------
// Kernel 1: gather (coalesced writes, streaming reads).
// One block per (n, diagonal row r); lane c handles column c.
// ---------------------------------------------------------------------------
__global__ void __launch_bounds__(U_) gather_kernel(const float* __restrict__ lp,
                                                    const int*   __restrict__ labels)
{
    const int r = (blockIdx.x % DD) + 1;     // shifted row 1..383
    const int n = blockIdx.x / DD;
    const int c = threadIdx.x;               // column 0..127

    const size_t rowbase = ((size_t)n * DD_PAD + r) * U_;

    int tb = r - 1 - c;                       // blank(t=tb, u=c)
    if (tb >= 0 && tb < T_) {
        float v = __ldcs(lp + ((((size_t)n * T_ + tb) * U_ + c) * V_) + (V_ - 1));
        g_blank[rowbase + c] = v * LOG2E;
    }
    int te = r - c;                           // emit(t=te, u=c-1)
    if (c >= 1 && te >= 0 && te < T_) {
        int lbl = __ldg(&labels[n * (U_ - 1) + (c - 1)]);
        float v = __ldcs(lp + ((((size_t)n * T_ + te) * U_ + (c - 1)) * V_) + lbl);
        g_emit[rowbase + c] = v * LOG2E;
    }
}

// ---------------------------------------------------------------------------
// Kernel 2: skewed-wavefront DP. 4 warps per example (4 SMSPs), ONE column
// per lane (u = tid). Warp w processes diagonal d at phase d + 8w; boundary
// alphas cross warps through a 32-slot smem ring; one __syncthreads per
// 8 phases (write->read gap = 9 phases, read->overwrite gap = 23 phases).
// Operands flow through an 8-slot named-register ring (prefetch distance 8).
// All transcendental math is MUFU (EX2/LG2) in the log2 domain.
// ---------------------------------------------------------------------------
#define PHASE(k)                                                              \
    {                                                                         \
        const int d = P0 + (k) - 8 * w;                                       \
        if (d >= 1 && d <= DD - 1) {                                          \
            float b = rb##k, e = re##k;                                       \
            float la = __shfl_up_sync(0xffffffffu, a, 1);                     \
            float left = (lane == 0)                                          \
                             ? ((w == 0) ? NEGF : bnd[w - 1][(d - 1) & 31])   \
                             : la;                                            \
            float x = a + b;                                                  \
            float y = left + e;                                               \
            float mx = fmaxf(x, y);                                           \
            float z  = ex2_fast(-fabsf(x - y));                               \
            a = mx + __log2f(1.0f + z);                                       \
            if (cap && d == target) saved = a;                                \
            if (lane == 31) bnd[w][d & 31] = a;                               \
        }                                                                     \
        {                                                                     \
            int rr = P0 + (k) - 8 * w + 8;                                    \
            rr = rr < 1 ? 1 : (rr > DD_PAD - 1 ? DD_PAD - 1 : rr);            \
            rb##k = __ldg(bl + (size_t)rr * U_ + u);                          \
            re##k = __ldg(em + (size_t)rr * U_ + u);                          \
        }                                                                     \
    }

#define PRELOAD(k)                                                            \
    float rb##k, re##k;                                                       \
    {                                                                         \
        int rr = (k) - 8 * w;                                                 \
        rr = rr < 1 ? 1 : rr;                                                 \
        rb##k = __ldg(bl + (size_t)rr * U_ + u);                              \
        re##k = __ldg(em + (size_t)rr * U_ + u);                              \
    }

__global__ void __launch_bounds__(128) dp_kernel(const int* __restrict__ lengths,
                                                 const int* __restrict__ label_lengths)
{
    __shared__ float bnd[4][32];   // [warp][diag & 31] lane-31 boundary alphas

    const int n    = blockIdx.x;
    const int tid  = threadIdx.x;
    const int w    = tid >> 5;
    const int lane = tid & 31;
    const int u    = tid;          // owned column

    bnd[w][lane] = NEGF;
    __syncthreads();

    const float* __restrict__ bl = g_blank + (size_t)n * DD_PAD * U_;
    const float* __restrict__ em = g_emit  + (size_t)n * DD_PAD * U_;

    const int t_idx  = __ldg(&lengths[n]) - 1;
    const int u_idx  = __ldg(&label_lengths[n]);
    const int target = t_idx + u_idx;

    float a     = (tid == 0) ? 0.0f : NEGF;   // alpha in log2 units
    float saved = 0.0f;
    const bool cap = (tid == u_idx);

    PRELOAD(0) PRELOAD(1) PRELOAD(2) PRELOAD(3)
    PRELOAD(4) PRELOAD(5) PRELOAD(6) PRELOAD(7)

    // Phases 0..407 in 51 groups of 8 (max needed phase: 382 + 24 = 406).
    for (int P0 = 0; P0 < 408; P0 += 8) {
        PHASE(0) PHASE(1) PHASE(2) PHASE(3)
        PHASE(4) PHASE(5) PHASE(6) PHASE(7)
        __syncthreads();
    }

    if (cap) {
        float bfin = __ldg(bl + (size_t)(target + 1) * U_ + u_idx); // blank(t_idx,u_idx)*log2e
        g_cost[n] = -(saved + bfin) * LN2;
    }
}

// ---------------------------------------------------------------------------
// Kernel 3: deterministic serial mean of the 16 per-example costs.
// ---------------------------------------------------------------------------
__global__ void finalize_kernel(float* __restrict__ out)
{
    float s = 0.0f;
#pragma unroll
    for (int i = 0; i < N_; ++i) s += g_cost[i];
    out[0] = s * (1.0f / N_);
}

// ---------------------------------------------------------------------------
extern "C" void kernel_launch(void* const* d_in, const int* in_sizes, int n_in,
                              void* d_out, int out_size)
{
    const float* log_probs     = (const float*)d_in[0];
    const int*   labels        = (const int*)  d_in[1];
    const int*   lengths       = (const int*)  d_in[2];
    const int*   label_lengths = (const int*)  d_in[3];
    float*       out           = (float*)d_out;

    gather_kernel  <<<N_ * DD, U_>>>(log_probs, labels);
    dp_kernel      <<<N_, 128>>>(lengths, label_lengths);
    finalize_kernel<<<1, 1>>>(out);
}

// round 13
// speedup vs baseline: 2.1450x; 1.7062x over previous
#include <cuda_runtime.h>
#include <cstdint>
#include <math.h>

// Problem shape (fixed): N=16, T=256, U=128, V=256, blank = V-1.
#define N_  16
#define T_  256
#define U_  128
#define V_  256
#define DD  383             // anti-diagonals d = 0..382
#define DD_PAD 400
#define LOG2E 1.4426950408889634f
#define LN2   0.6931471805599453f

// Scratch (allocation-free rule: __device__ globals, zero-initialized).
// SHIFTED diagonal-major layout holding PROBABILITIES (linear domain):
//   pb(n,t,u)=exp(blank lp) at [n][t+u+1][u]; pe(n,t,u)=exp(emit lp) at
//   [n][t+u+1][u+1]. Unwritten slots stay 0.0 = "impossible transition".
__device__ __align__(16) float g_pb[N_ * DD_PAD * U_];
__device__ __align__(16) float g_pe[N_ * DD_PAD * U_];
__device__ float g_cost[N_];

// MUFU EX2 (plain exp2f is a slow software routine without fast-math).
__device__ __forceinline__ float ex2_fast(float x) {
    float y;
    asm("ex2.approx.ftz.f32 %0, %1;" : "=f"(y) : "f"(x));
    return y;
}

// ---------------------------------------------------------------------------
// Kernel 1: gather + exponentiate. One block per (n, diagonal row r).
// Coalesced writes, streaming scattered reads; EX2 is free (DRAM-bound).
// ---------------------------------------------------------------------------
__global__ void __launch_bounds__(U_) gather_kernel(const float* __restrict__ lp,
                                                    const int*   __restrict__ labels)
{
    const int r = (blockIdx.x % DD) + 1;     // shifted row 1..383
    const int n = blockIdx.x / DD;
    const int c = threadIdx.x;               // column 0..127

    const size_t rowbase = ((size_t)n * DD_PAD + r) * U_;

    int tb = r - 1 - c;                       // blank(t=tb, u=c)
    if (tb >= 0 && tb < T_) {
        float v = __ldcs(lp + ((((size_t)n * T_ + tb) * U_ + c) * V_) + (V_ - 1));
        g_pb[rowbase + c] = ex2_fast(v * LOG2E);
    }
    int te = r - c;                           // emit(t=te, u=c-1)
    if (c >= 1 && te >= 0 && te < T_) {
        int lbl = __ldg(&labels[n * (U_ - 1) + (c - 1)]);
        float v = __ldcs(lp + ((((size_t)n * T_ + te) * U_ + (c - 1)) * V_) + lbl);
        g_pe[rowbase + c] = ex2_fast(v * LOG2E);
    }
}

// ---------------------------------------------------------------------------
// Kernel 2: LINEAR-DOMAIN wavefront DP. One warp per example, 4 cols/lane.
// alpha update = pure FMA (no MUFU on the chain). Scaled-forward: every 4
// diagonals rescale by 2^k derived from the warp max (redux.sync on float
// bits; alphas >= 0 so u32 order == float order), accumulating exponent G.
// Operand rows flow through a 16-slot cp.async smem ring (no barriers:
// each thread async-copies exactly the 16B it later reads).
// ---------------------------------------------------------------------------
#define DP_STEP(bv, ev, dcur)                                                 \
    {                                                                         \
        float la = __shfl_up_sync(0xffffffffu, a3, 1);                        \
        float l0 = (tx == 0) ? 0.0f : la;                                     \
        float n0 = fmaf(a0, (bv).x, l0 * (ev).x);                             \
        float n1 = fmaf(a1, (bv).y, a0 * (ev).y);                             \
        float n2 = fmaf(a2, (bv).z, a1 * (ev).z);                             \
        float n3 = fmaf(a3, (bv).w, a2 * (ev).w);                             \
        a0 = n0; a1 = n1; a2 = n2; a3 = n3;                                   \
        if ((dcur) == target && cap) {                                        \
            saved  = (ci == 0) ? n0 : (ci == 1) ? n1 : (ci == 2) ? n2 : n3;   \
            savedG = G;                                                       \
        }                                                                     \
    }

#define ISSUE_ROW(rr)                                                         \
    {                                                                         \
        int _rrc = (rr) < (DD_PAD - 1) ? (rr) : (DD_PAD - 1);                 \
        unsigned _slot = ((unsigned)(rr) & 15u) * (U_ * 4u) + lane_off;       \
        const float* _gb = bl + (size_t)_rrc * U_ + 4 * tx;                   \
        const float* _ge = em + (size_t)_rrc * U_ + 4 * tx;                   \
        asm volatile("cp.async.ca.shared.global [%0], [%1], 16;"              \
                     :: "r"(sb_base + _slot), "l"(_gb));                      \
        asm volatile("cp.async.ca.shared.global [%0], [%1], 16;"              \
                     :: "r"(se_base + _slot), "l"(_ge));                      \
    }

#define DP_PAIR(p)                                                            \
    {                                                                         \
        asm volatile("cp.async.wait_group 6;" ::: "memory");                  \
        ISSUE_ROW(2 * (p) + 15);                                              \
        ISSUE_ROW(2 * (p) + 16);                                              \
        asm volatile("cp.async.commit_group;" ::: "memory");                  \
        const int _d1 = 2 * (p) + 1;                                          \
        {                                                                     \
            const int _s = _d1 & 15;                                          \
            float4 b = *(const float4*)&sb[_s * U_ + 4 * tx];                 \
            float4 e = *(const float4*)&se[_s * U_ + 4 * tx];                 \
            DP_STEP(b, e, _d1);                                               \
        }                                                                     \
        {                                                                     \
            const int _d2 = _d1 + 1;                                          \
            const int _s = _d2 & 15;                                          \
            float4 b = *(const float4*)&sb[_s * U_ + 4 * tx];                 \
            float4 e = *(const float4*)&se[_s * U_ + 4 * tx];                 \
            DP_STEP(b, e, _d2);                                               \
        }                                                                     \
    }

__global__ void __launch_bounds__(32) dp_kernel(const int* __restrict__ lengths,
                                                const int* __restrict__ label_lengths)
{
    __shared__ __align__(16) float sb[16 * U_];   // pb ring, slot = row & 15
    __shared__ __align__(16) float se[16 * U_];   // pe ring

    const int n  = blockIdx.x;
    const int tx = threadIdx.x;                   // owns u = 4*tx .. 4*tx+3

    const float* __restrict__ bl = g_pb + (size_t)n * DD_PAD * U_;
    const float* __restrict__ em = g_pe + (size_t)n * DD_PAD * U_;

    const int t_idx  = __ldg(&lengths[n]) - 1;
    const int u_idx  = __ldg(&label_lengths[n]);
    const int target = t_idx + u_idx;

    // alpha scaled by 2^G; seed alpha(0,0)=1 stored as 2^60 (window bias).
    float a0 = (tx == 0) ? __uint_as_float((127u + 60u) << 23) : 0.0f;
    float a1 = 0.0f, a2 = 0.0f, a3 = 0.0f;
    int   G = 60, savedG = 0;
    float saved = 1.0f;
    const bool cap = (tx == (u_idx >> 2));
    const int  ci  = u_idx & 3;

    const unsigned sb_base = (unsigned)__cvta_generic_to_shared(sb);
    const unsigned se_base = (unsigned)__cvta_generic_to_shared(se);
    const unsigned lane_off = 16u * (unsigned)tx;

    // Prologue: issue rows 1..14 (7 commit groups).
#pragma unroll
    for (int q = 0; q < 7; ++q) {
        ISSUE_ROW(2 * q + 1);
        ISSUE_ROW(2 * q + 2);
        asm volatile("cp.async.commit_group;" ::: "memory");
    }

    // Pending rescale info: max-bits measured one group (4 diagonals) ago.
    unsigned mprev = (127u + 60u) << 23;          // => k = 0 on first apply

    // 95 groups x 2 pairs = diagonals 1..380; tail pair covers 381,382.
    for (int gq = 0; gq < 95; ++gq) {
        // Apply rescale derived from the max 4 diagonals ago.
        {
            int ef = (int)(mprev >> 23);
            int k  = 187 - ef;
            k = k > 120 ? 120 : (k < -120 ? -120 : k);
            float factor = __uint_as_float((unsigned)(127 + k) << 23);
            a0 *= factor; a1 *= factor; a2 *= factor; a3 *= factor;
            G += k;
        }

        DP_PAIR(2 * gq);
        DP_PAIR(2 * gq + 1);

        // Launch warp-max (float bits; alphas >= 0) for the NEXT group.
        {
            float m01 = fmaxf(a0, a1), m23 = fmaxf(a2, a3);
            float m   = fmaxf(m01, m23);
            mprev = __reduce_max_sync(0xffffffffu, __float_as_uint(m));
        }
    }

    DP_PAIR(190);   // diagonals 381, 382

    if (cap) {
        // log2(alpha_true(target)) = log2(saved) - savedG
        float lpb_fin = __log2f(bl[(size_t)(target + 1) * U_ + u_idx]); // log2 blank prob
        float l2 = __log2f(saved) - (float)savedG + lpb_fin;
        g_cost[n] = -l2 * LN2;
    }
}

// ---------------------------------------------------------------------------
// Kernel 3: deterministic serial mean of the 16 per-example costs.
// ---------------------------------------------------------------------------
__global__ void finalize_kernel(float* __restrict__ out)
{
    float s = 0.0f;
#pragma unroll
    for (int i = 0; i < N_; ++i) s += g_cost[i];
    out[0] = s * (1.0f / N_);
}

// ---------------------------------------------------------------------------
extern "C" void kernel_launch(void* const* d_in, const int* in_sizes, int n_in,
                              void* d_out, int out_size)
{
    const float* log_probs     = (const float*)d_in[0];
    const int*   labels        = (const int*)  d_in[1];
    const int*   lengths       = (const int*)  d_in[2];
    const int*   label_lengths = (const int*)  d_in[3];
    float*       out           = (float*)d_out;

    gather_kernel  <<<N_ * DD, U_>>>(log_probs, labels);
    dp_kernel      <<<N_, 32>>>(lengths, label_lengths);
    finalize_kernel<<<1, 1>>>(out);
}